// round 9
// baseline (speedup 1.0000x reference)
#include <cuda_runtime.h>

#define K 32
#define NBUCKET 33
#define NELEM (32*64*1024)
#define THREADS 128
#define GRID 888          // 148 SMs x 6 CTAs (smem-limited) = exactly one wave
#define FULL 0xffffffffu

// Global accumulators; last block self-cleans for graph replay.
__device__ float g_A[NBUCKET];   // bucket sums of a2 (by rank m)
__device__ float g_B[NBUCKET];   // bucket sums of b2
__device__ float g_Q;
__device__ unsigned int g_count;

__device__ __forceinline__ float ex2f_(float x) {
    float r; asm("ex2.approx.ftz.f32 %0, %1;" : "=f"(r) : "f"(x)); return r;
}
__device__ __forceinline__ float rsqf_(float x) {
    float r; asm("rsqrt.approx.ftz.f32 %0, %1;" : "=f"(r) : "f"(x)); return r;
}

__global__ __launch_bounds__(THREADS, 6)
void ssq_kernel(const float* __restrict__ x,
                const float* __restrict__ bins,
                float* __restrict__ out)
{
    __shared__ float  sbins[64];           // sorted bins + inf pad (covers m up to 32+s)
    __shared__ float4 sTabP[NBUCKET];      // {P10, P5, PB, 0} exclusive prefixes
    __shared__ float4 sTabQ[NBUCKET];      // {Q10, Q5, QB, 0} inclusive suffixes
    __shared__ float  sEpsB;
    __shared__ float2 sSlab[NBUCKET * THREADS];  // [m][tid] (a2,b2), conflict-free
    __shared__ float  sQw[THREADS/32];
    __shared__ int    sLast;

    const int tid  = threadIdx.x;
    const int lane = tid & 31;
    const int warp = tid >> 5;

    const float C5  = 7.21347520444482f;    // 5*log2(e)
    const float C10 = 14.42695040888963f;   // 10*log2(e)

    // ---- Prologue (warp 0): sort bins, build prefix/suffix tables ----
    if (warp == 0) {
        float v = __ldg(&bins[lane]);
        #pragma unroll
        for (int kk = 2; kk <= 32; kk <<= 1) {
            #pragma unroll
            for (int j = kk >> 1; j > 0; j >>= 1) {
                float w = __shfl_xor_sync(FULL, v, j);
                bool takeMin = (((lane & j) == 0) == ((lane & kk) == 0));
                v = takeMin ? fminf(v, w) : fmaxf(v, w);
            }
        }
        sbins[lane]      = v;          // ascending
        sbins[lane + 32] = 3.0e38f;    // pad: never <= any finite x

        float sb = v;
        #pragma unroll
        for (int m = 16; m > 0; m >>= 1) sb += __shfl_xor_sync(FULL, sb, m);
        if (lane == 0) sEpsB = 1e-10f * sb;

        float e10 = ex2f_( C10 * v), f10 = ex2f_(-C10 * v);
        float e5  = ex2f_( C5  * v), f5  = ex2f_(-C5  * v);
        float eb  = e10 * v,         fb  = f10 * v;

        float p10 = e10, p5 = e5, pb = eb;          // inclusive prefix
        #pragma unroll
        for (int d = 1; d < 32; d <<= 1) {
            float t0 = __shfl_up_sync(FULL, p10, d);
            float t1 = __shfl_up_sync(FULL, p5,  d);
            float t2 = __shfl_up_sync(FULL, pb,  d);
            if (lane >= d) { p10 += t0; p5 += t1; pb += t2; }
        }
        float q10 = f10, q5 = f5, qb = fb;          // inclusive suffix
        #pragma unroll
        for (int d = 1; d < 32; d <<= 1) {
            float t0 = __shfl_down_sync(FULL, q10, d);
            float t1 = __shfl_down_sync(FULL, q5,  d);
            float t2 = __shfl_down_sync(FULL, qb,  d);
            if (lane + d < 32) { q10 += t0; q5 += t1; qb += t2; }
        }
        sTabP[lane + 1] = make_float4(p10, p5, pb, 0.f);
        sTabQ[lane]     = make_float4(q10, q5, qb, 0.f);
        if (lane == 0) {
            sTabP[0]  = make_float4(0.f, 0.f, 0.f, 0.f);
            sTabQ[32] = make_float4(0.f, 0.f, 0.f, 0.f);
        }
    }
    // Zero the bucket slab (all threads).
    #pragma unroll
    for (int i = 0; i < NBUCKET; i++)
        sSlab[i * THREADS + tid] = make_float2(0.f, 0.f);
    __syncthreads();

    const float epsB  = sEpsB;
    const float SCALE = 0x1p-64f;       // range guard for a2/b2 sums
    const float b31r  = sbins[31];      // register-cached search levels 1-2
    const float b15r  = sbins[15];
    float qacc = 0.f;

    const int gtid = blockIdx.x * THREADS + tid;
    const int stride = GRID * THREADS;
    const float4* x4 = (const float4*)x;
    float4* o4 = (float4*)out;
    const int n4 = NELEM / 4;

    #pragma unroll 1
    for (int i = gtid; i < n4; i += stride) {
        float4 xv = x4[i];
        float xs[4] = {xv.x, xv.y, xv.z, xv.w};
        float os[4], a2s[4], b2s[4]; int ms[4];

        #pragma unroll
        for (int c = 0; c < 4; c++) {
            const float xe = xs[c];
            const float A  = ex2f_(-C5 * xe);   // exp(-5x)
            const float B  = ex2f_( C5 * xe);   // exp(+5x)
            const float A2 = A * A;             // exp(-10x)
            const float B2 = B * B;             // exp(+10x)

            // Rank m = #{b_k <= x}. Levels s=32,16 from registers, 4 LDS levels.
            int m = (b31r <= xe) ? 32 : ((b15r <= xe) ? 16 : 0);
            #pragma unroll
            for (int s = 8; s > 0; s >>= 1)
                m += (sbins[m + s - 1] <= xe) ? s : 0;

            const float4 tp = sTabP[m];
            const float4 tq = sTabQ[m];
            const float S  = fmaf(A2, tp.x, B2 * tq.x);
            const float Hs = fmaf(A,  tp.y, B  * tq.y);
            const float bR = fmaf(A2, tp.z, B2 * tq.z);
            const float rs = rsqf_(S);
            const float invS = rs * rs;
            qacc = fmaf(Hs, rs, qacc);                // sum_k sqrt(soft_k)
            os[c]  = fmaf(bR, invS, epsB);            // bit_code element
            a2s[c] = (A2 * invS) * SCALE;
            b2s[c] = (B2 * invS) * SCALE;
            ms[c]  = m;
        }
        o4[i] = make_float4(os[0], os[1], os[2], os[3]);

        // Rank-bucket accumulation: thread-private column -> conflict-free.
        #pragma unroll
        for (int c = 0; c < 4; c++) {
            const int idx = ms[c] * THREADS + tid;
            float2 v = sSlab[idx];
            v.x += a2s[c]; v.y += b2s[c];
            sSlab[idx] = v;
        }
    }

    // ---- Block reduce ----
    #pragma unroll
    for (int m = 16; m > 0; m >>= 1) qacc += __shfl_xor_sync(FULL, qacc, m);
    if (lane == 0) sQw[warp] = qacc;
    __syncthreads();

    // Each warp reduces buckets warp, warp+4, ... over the 128 thread columns.
    for (int m = warp; m < NBUCKET; m += THREADS/32) {
        float ta = 0.f, tb = 0.f;
        #pragma unroll
        for (int t = 0; t < THREADS; t += 32) {
            float2 v = sSlab[m * THREADS + t + lane];
            ta += v.x; tb += v.y;
        }
        #pragma unroll
        for (int d = 16; d > 0; d >>= 1) {
            ta += __shfl_xor_sync(FULL, ta, d);
            tb += __shfl_xor_sync(FULL, tb, d);
        }
        if (lane == 0) {
            atomicAdd(&g_A[m], ta);
            atomicAdd(&g_B[m], tb);
        }
    }
    if (tid == 0) {
        float q = 0.f;
        #pragma unroll
        for (int w = 0; w < THREADS/32; w++) q += sQw[w];
        atomicAdd(&g_Q, q);
    }

    // ---- Last-block finalize (self-cleaning) ----
    if (tid == 0) {
        __threadfence();
        unsigned int arrived = atomicAdd(&g_count, 1u);
        sLast = (arrived == GRID - 1u) ? 1 : 0;
    }
    __syncthreads();
    if (sLast) {
        __threadfence();
        if (tid < 32) {
            volatile float* va = g_A;
            volatile float* vb = g_B;
            // suffix over A-buckets (m = lane+1 .. 32)
            float sa = va[lane + 1];
            #pragma unroll
            for (int d = 1; d < 32; d <<= 1) {
                float t = __shfl_down_sync(FULL, sa, d);
                if (lane + d < 32) sa += t;
            }
            // prefix over B-buckets (m = 0 .. lane)
            float sbv = vb[lane];
            #pragma unroll
            for (int d = 1; d < 32; d <<= 1) {
                float t = __shfl_up_sync(FULL, sbv, d);
                if (lane >= d) sbv += t;
            }
            float bk   = sbins[lane];
            float E10k = ex2f_( C10 * bk);
            float F10k = ex2f_(-C10 * bk);
            float u = E10k * sa + F10k * sbv;          // scaled by 2^-64
            float p = fmaf(u, 0x1p43f, 1e-10f);        // *2^64/NELEM + EPS
            float e = -p * logf(p);
            #pragma unroll
            for (int d = 16; d > 0; d >>= 1)
                e += __shfl_xor_sync(FULL, e, d);
            if (lane == 0) {
                volatile float* vq = &g_Q;
                out[NELEM]     = e;                              // code entropy
                out[NELEM + 1] = 0.f;                            // TAU
                out[NELEM + 2] = vq[0] * (1.0f / (float)NELEM);  // quant loss
                out[NELEM + 3] = 0.f;                            // TAU2
            }
        }
        __syncthreads();
        if (tid < NBUCKET) { g_A[tid] = 0.f; g_B[tid] = 0.f; }
        if (tid == 0) { g_Q = 0.f; g_count = 0u; }
    }
}

extern "C" void kernel_launch(void* const* d_in, const int* in_sizes, int n_in,
                              void* d_out, int out_size)
{
    const float* x    = (const float*)d_in[0];
    const float* bins = (const float*)d_in[1];
    if (n_in >= 2 && in_sizes[0] == K && in_sizes[1] != K) {
        const float* tmp = x; x = bins; bins = tmp;
    }
    float* out = (float*)d_out;

    ssq_kernel<<<GRID, THREADS>>>(x, bins, out);
}

// round 10
// speedup vs baseline: 1.4714x; 1.4714x over previous
#include <cuda_runtime.h>

#define K 32
#define NBUCKET 33
#define NELEM (32*64*1024)
#define THREADS 128
#define GRID 592          // 148 SMs x 4 CTAs = exactly one wave
#define FULL 0xffffffffu

// Global accumulators; last block self-cleans for graph replay.
__device__ float g_A[NBUCKET];   // bucket sums of a2 (by rank m)
__device__ float g_B[NBUCKET];   // bucket sums of b2
__device__ float g_Q;
__device__ unsigned int g_count;

__device__ __forceinline__ float ex2f_(float x) {
    float r; asm("ex2.approx.ftz.f32 %0, %1;" : "=f"(r) : "f"(x)); return r;
}
__device__ __forceinline__ float rsqf_(float x) {
    float r; asm("rsqrt.approx.ftz.f32 %0, %1;" : "=f"(r) : "f"(x)); return r;
}

__global__ __launch_bounds__(THREADS, 4)
void ssq_kernel(const float* __restrict__ x,
                const float* __restrict__ bins,
                float* __restrict__ out)
{
    __shared__ float  sbins[32];           // sorted bins
    __shared__ float4 sTabP[NBUCKET];      // {P10, P5, PB, 0} exclusive prefixes
    __shared__ float4 sTabQ[NBUCKET];      // {Q10, Q5, QB, 0} inclusive suffixes
    __shared__ float  sEpsB;
    __shared__ float2 sSlab[NBUCKET * THREADS];  // [m][tid] (a2,b2), conflict-free
    __shared__ float  sQw[THREADS/32];
    __shared__ int    sLast;

    const int tid  = threadIdx.x;
    const int lane = tid & 31;
    const int warp = tid >> 5;

    const float C5  = 7.21347520444482f;    // 5*log2(e)
    const float C10 = 14.42695040888963f;   // 10*log2(e)

    // ---- Prologue (warp 0): sort bins, build prefix/suffix tables ----
    if (warp == 0) {
        float v = __ldg(&bins[lane]);
        #pragma unroll
        for (int kk = 2; kk <= 32; kk <<= 1) {
            #pragma unroll
            for (int j = kk >> 1; j > 0; j >>= 1) {
                float w = __shfl_xor_sync(FULL, v, j);
                bool takeMin = (((lane & j) == 0) == ((lane & kk) == 0));
                v = takeMin ? fminf(v, w) : fmaxf(v, w);
            }
        }
        sbins[lane] = v;               // ascending

        float sb = v;
        #pragma unroll
        for (int m = 16; m > 0; m >>= 1) sb += __shfl_xor_sync(FULL, sb, m);
        if (lane == 0) sEpsB = 1e-10f * sb;

        float e10 = ex2f_( C10 * v), f10 = ex2f_(-C10 * v);
        float e5  = ex2f_( C5  * v), f5  = ex2f_(-C5  * v);
        float eb  = e10 * v,         fb  = f10 * v;

        float p10 = e10, p5 = e5, pb = eb;          // inclusive prefix
        #pragma unroll
        for (int d = 1; d < 32; d <<= 1) {
            float t0 = __shfl_up_sync(FULL, p10, d);
            float t1 = __shfl_up_sync(FULL, p5,  d);
            float t2 = __shfl_up_sync(FULL, pb,  d);
            if (lane >= d) { p10 += t0; p5 += t1; pb += t2; }
        }
        float q10 = f10, q5 = f5, qb = fb;          // inclusive suffix
        #pragma unroll
        for (int d = 1; d < 32; d <<= 1) {
            float t0 = __shfl_down_sync(FULL, q10, d);
            float t1 = __shfl_down_sync(FULL, q5,  d);
            float t2 = __shfl_down_sync(FULL, qb,  d);
            if (lane + d < 32) { q10 += t0; q5 += t1; qb += t2; }
        }
        sTabP[lane + 1] = make_float4(p10, p5, pb, 0.f);
        sTabQ[lane]     = make_float4(q10, q5, qb, 0.f);
        if (lane == 0) {
            sTabP[0]  = make_float4(0.f, 0.f, 0.f, 0.f);
            sTabQ[32] = make_float4(0.f, 0.f, 0.f, 0.f);
        }
    }
    // Zero the bucket slab (all threads).
    #pragma unroll
    for (int i = 0; i < NBUCKET; i++)
        sSlab[i * THREADS + tid] = make_float2(0.f, 0.f);
    __syncthreads();

    // Sorted bins into per-thread registers: rank = 32 INDEPENDENT compares,
    // no dependent-LDS chain (the R7/R9 latency bottleneck).
    float rb[K];
    #pragma unroll
    for (int k = 0; k < K; k++) rb[k] = sbins[k];

    const float epsB  = sEpsB;
    const float SCALE = 0x1p-64f;       // range guard for a2/b2 sums
    float qacc = 0.f;

    const int gtid = blockIdx.x * THREADS + tid;
    const int stride = GRID * THREADS;
    const float4* x4 = (const float4*)x;
    float4* o4 = (float4*)out;
    const int n4 = NELEM / 4;

    #pragma unroll 1
    for (int i = gtid; i < n4; i += stride) {
        float4 xv = x4[i];
        float xs[4] = {xv.x, xv.y, xv.z, xv.w};
        float os[4], a2s[4], b2s[4]; int ms[4];

        #pragma unroll
        for (int c = 0; c < 4; c++) {
            const float xe = xs[c];
            const float A  = ex2f_(-C5 * xe);   // exp(-5x)
            const float B  = ex2f_( C5 * xe);   // exp(+5x)
            const float A2 = A * A;             // exp(-10x)
            const float B2 = B * B;             // exp(+10x)

            // Rank m = #{b_k <= x}: 32 independent register compares.
            int m = 0;
            #pragma unroll
            for (int k = 0; k < K; k++) m += (xe >= rb[k]) ? 1 : 0;

            const float4 tp = sTabP[m];
            const float4 tq = sTabQ[m];
            const float S  = fmaf(A2, tp.x, B2 * tq.x);
            const float Hs = fmaf(A,  tp.y, B  * tq.y);
            const float bR = fmaf(A2, tp.z, B2 * tq.z);
            const float rs = rsqf_(S);
            const float invS = rs * rs;
            qacc = fmaf(Hs, rs, qacc);                // sum_k sqrt(soft_k)
            os[c]  = fmaf(bR, invS, epsB);            // bit_code element
            a2s[c] = (A2 * invS) * SCALE;
            b2s[c] = (B2 * invS) * SCALE;
            ms[c]  = m;
        }
        o4[i] = make_float4(os[0], os[1], os[2], os[3]);

        // Rank-bucket accumulation: thread-private column -> conflict-free.
        #pragma unroll
        for (int c = 0; c < 4; c++) {
            const int idx = ms[c] * THREADS + tid;
            float2 v = sSlab[idx];
            v.x += a2s[c]; v.y += b2s[c];
            sSlab[idx] = v;
        }
    }

    // ---- Block reduce ----
    #pragma unroll
    for (int m = 16; m > 0; m >>= 1) qacc += __shfl_xor_sync(FULL, qacc, m);
    if (lane == 0) sQw[warp] = qacc;
    __syncthreads();

    // Each warp reduces buckets warp, warp+4, ... over the 128 thread columns.
    for (int m = warp; m < NBUCKET; m += THREADS/32) {
        float ta = 0.f, tb = 0.f;
        #pragma unroll
        for (int t = 0; t < THREADS; t += 32) {
            float2 v = sSlab[m * THREADS + t + lane];
            ta += v.x; tb += v.y;
        }
        #pragma unroll
        for (int d = 16; d > 0; d >>= 1) {
            ta += __shfl_xor_sync(FULL, ta, d);
            tb += __shfl_xor_sync(FULL, tb, d);
        }
        if (lane == 0) {
            atomicAdd(&g_A[m], ta);
            atomicAdd(&g_B[m], tb);
        }
    }
    if (tid == 0) {
        float q = 0.f;
        #pragma unroll
        for (int w = 0; w < THREADS/32; w++) q += sQw[w];
        atomicAdd(&g_Q, q);
    }

    // ---- Last-block finalize (self-cleaning) ----
    if (tid == 0) {
        __threadfence();
        unsigned int arrived = atomicAdd(&g_count, 1u);
        sLast = (arrived == GRID - 1u) ? 1 : 0;
    }
    __syncthreads();
    if (sLast) {
        __threadfence();
        if (tid < 32) {
            volatile float* va = g_A;
            volatile float* vb = g_B;
            // suffix over A-buckets (m = lane+1 .. 32)
            float sa = va[lane + 1];
            #pragma unroll
            for (int d = 1; d < 32; d <<= 1) {
                float t = __shfl_down_sync(FULL, sa, d);
                if (lane + d < 32) sa += t;
            }
            // prefix over B-buckets (m = 0 .. lane)
            float sbv = vb[lane];
            #pragma unroll
            for (int d = 1; d < 32; d <<= 1) {
                float t = __shfl_up_sync(FULL, sbv, d);
                if (lane >= d) sbv += t;
            }
            float bk   = sbins[lane];
            float E10k = ex2f_( C10 * bk);
            float F10k = ex2f_(-C10 * bk);
            float u = E10k * sa + F10k * sbv;          // scaled by 2^-64
            float p = fmaf(u, 0x1p43f, 1e-10f);        // *2^64/NELEM + EPS
            float e = -p * logf(p);
            #pragma unroll
            for (int d = 16; d > 0; d >>= 1)
                e += __shfl_xor_sync(FULL, e, d);
            if (lane == 0) {
                volatile float* vq = &g_Q;
                out[NELEM]     = e;                              // code entropy
                out[NELEM + 1] = 0.f;                            // TAU
                out[NELEM + 2] = vq[0] * (1.0f / (float)NELEM);  // quant loss
                out[NELEM + 3] = 0.f;                            // TAU2
            }
        }
        __syncthreads();
        if (tid < NBUCKET) { g_A[tid] = 0.f; g_B[tid] = 0.f; }
        if (tid == 0) { g_Q = 0.f; g_count = 0u; }
    }
}

extern "C" void kernel_launch(void* const* d_in, const int* in_sizes, int n_in,
                              void* d_out, int out_size)
{
    const float* x    = (const float*)d_in[0];
    const float* bins = (const float*)d_in[1];
    if (n_in >= 2 && in_sizes[0] == K && in_sizes[1] != K) {
        const float* tmp = x; x = bins; bins = tmp;
    }
    float* out = (float*)d_out;

    ssq_kernel<<<GRID, THREADS>>>(x, bins, out);
}